// round 1
// baseline (speedup 1.0000x reference)
#include <cuda_runtime.h>

#define D_MODEL   1024
#define NUM_HEADS 16
#define HEAD_DIM  64
#define BATCH     2
#define SEQ       2048
#define NTOK      (BATCH * SEQ)   // 4096

// Scratch (device globals: no allocation allowed in kernel_launch)
__device__ float g_q[NTOK * D_MODEL];     // [B,H,S,hd]
__device__ float g_k[NTOK * D_MODEL];     // [B,H,S,hd]
__device__ float g_v[NTOK * D_MODEL];     // [B,H,S,hd]
__device__ float g_attn[NTOK * D_MODEL];  // [B,S,D]

// ---------------------------------------------------------------------------
// SGEMM: C[M=4096, N=1024] = A[4096,1024] @ W[1024,1024] + bias[1024]
// BM=BN=128, BK=8, 256 threads, 8x8 per thread.
// SPLIT_HEADS=1: write to [B,H,S,hd] layout; else direct [row, col].
// ---------------------------------------------------------------------------
template<int SPLIT_HEADS>
__global__ __launch_bounds__(256) void gemm_bias_kernel(
    const float* __restrict__ A,
    const float* __restrict__ W,
    const float* __restrict__ bias,
    float* __restrict__ C)
{
    __shared__ float As[8][128];
    __shared__ float Bs[8][128];

    const int tx  = threadIdx.x;              // 0..255
    const int row = (tx >> 4) * 8;            // 0..120
    const int col = (tx & 15) * 8;            // 0..120
    const int m0  = blockIdx.y * 128;
    const int n0  = blockIdx.x * 128;

    float acc[8][8];
#pragma unroll
    for (int i = 0; i < 8; i++)
#pragma unroll
        for (int j = 0; j < 8; j++) acc[i][j] = 0.f;

    const int am = tx >> 1;                   // 0..127
    const int ak = (tx & 1) * 4;              // 0 or 4
    const int bk = tx >> 5;                   // 0..7
    const int bc = (tx & 31) * 4;             // 0..124

    for (int k0 = 0; k0 < D_MODEL; k0 += 8) {
        float4 av = *(const float4*)(A + (size_t)(m0 + am) * D_MODEL + k0 + ak);
        float4 bv = *(const float4*)(W + (size_t)(k0 + bk) * D_MODEL + n0 + bc);
        __syncthreads();
        As[ak + 0][am] = av.x;
        As[ak + 1][am] = av.y;
        As[ak + 2][am] = av.z;
        As[ak + 3][am] = av.w;
        *(float4*)&Bs[bk][bc] = bv;
        __syncthreads();
#pragma unroll
        for (int kk = 0; kk < 8; kk++) {
            float4 a0 = *(const float4*)&As[kk][row];
            float4 a1 = *(const float4*)&As[kk][row + 4];
            float4 b0 = *(const float4*)&Bs[kk][col];
            float4 b1 = *(const float4*)&Bs[kk][col + 4];
            float a[8] = {a0.x, a0.y, a0.z, a0.w, a1.x, a1.y, a1.z, a1.w};
            float b[8] = {b0.x, b0.y, b0.z, b0.w, b1.x, b1.y, b1.z, b1.w};
#pragma unroll
            for (int i = 0; i < 8; i++)
#pragma unroll
                for (int j = 0; j < 8; j++)
                    acc[i][j] += a[i] * b[j];
        }
    }

#pragma unroll
    for (int i = 0; i < 8; i++) {
        int gm = m0 + row + i;
#pragma unroll
        for (int j = 0; j < 8; j++) {
            int gn = n0 + col + j;
            float v = acc[i][j] + bias[gn];
            if (SPLIT_HEADS) {
                int b  = gm >> 11;          // / SEQ
                int s  = gm & (SEQ - 1);
                int h  = gn >> 6;           // / HEAD_DIM
                int dh = gn & (HEAD_DIM - 1);
                C[(((size_t)(b * NUM_HEADS + h) * SEQ) + s) * HEAD_DIM + dh] = v;
            } else {
                C[(size_t)gm * D_MODEL + gn] = v;
            }
        }
    }
}

// ---------------------------------------------------------------------------
// Flash attention (fp32, causal). 1 thread = 1 query row.
// Block: 128 threads = 128 query rows. KV streamed in tiles of 64 rows.
// Online softmax in 16-column sub-chunks (keeps s[] fully unrolled in regs).
// ---------------------------------------------------------------------------
#define FTILE 64

__global__ __launch_bounds__(128, 1) void flash_kernel(
    const float* __restrict__ Q,
    const float* __restrict__ Kg,
    const float* __restrict__ Vg,
    float* __restrict__ Og)
{
    __shared__ float4 Ks[FTILE][16];
    __shared__ float4 Vs[FTILE][16];

    const int bh  = blockIdx.y;                              // 0..31 (b*16+h)
    const int qt  = (int)gridDim.x - 1 - (int)blockIdx.x;    // heavy tiles first
    const int tid = threadIdx.x;
    const int m_global = qt * 128 + tid;

    const float* qptr = Q + ((size_t)bh * SEQ + m_global) * HEAD_DIM;
    const float* kb   = Kg + (size_t)bh * SEQ * HEAD_DIM;
    const float* vb   = Vg + (size_t)bh * SEQ * HEAD_DIM;

    const float scale = 0.125f;  // 1/sqrt(64)
    float4 q[16];
#pragma unroll
    for (int i = 0; i < 16; i++) {
        q[i] = ((const float4*)qptr)[i];
        q[i].x *= scale; q[i].y *= scale; q[i].z *= scale; q[i].w *= scale;
    }

    float4 o[16];
#pragma unroll
    for (int i = 0; i < 16; i++) o[i] = make_float4(0.f, 0.f, 0.f, 0.f);
    float m_run = -1e30f, l = 0.f;

    const int kv_end = qt * 128 + 128;
    for (int j0 = 0; j0 < kv_end; j0 += FTILE) {
        __syncthreads();
#pragma unroll
        for (int r = 0; r < 8; r++) {
            int idx  = tid + r * 128;     // 0..1023
            int rw   = idx >> 4;
            int c    = idx & 15;
            Ks[rw][c] = ((const float4*)(kb + (size_t)(j0 + rw) * HEAD_DIM))[c];
            Vs[rw][c] = ((const float4*)(vb + (size_t)(j0 + rw) * HEAD_DIM))[c];
        }
        __syncthreads();

#pragma unroll 1
        for (int jj = 0; jj < FTILE; jj += 16) {
            int jbase = j0 + jj;
            if (jbase > m_global) break;   // causal: this thread is done here

            float s[16];
            float smax = -1e30f;
#pragma unroll
            for (int j = 0; j < 16; j++) {
                float a0 = 0.f, a1 = 0.f, a2 = 0.f, a3 = 0.f;
#pragma unroll
                for (int i = 0; i < 16; i += 4) {
                    float4 k0 = Ks[jj + j][i + 0];
                    float4 k1 = Ks[jj + j][i + 1];
                    float4 k2 = Ks[jj + j][i + 2];
                    float4 k3 = Ks[jj + j][i + 3];
                    a0 += q[i + 0].x * k0.x + q[i + 0].y * k0.y + q[i + 0].z * k0.z + q[i + 0].w * k0.w;
                    a1 += q[i + 1].x * k1.x + q[i + 1].y * k1.y + q[i + 1].z * k1.z + q[i + 1].w * k1.w;
                    a2 += q[i + 2].x * k2.x + q[i + 2].y * k2.y + q[i + 2].z * k2.z + q[i + 2].w * k2.w;
                    a3 += q[i + 3].x * k3.x + q[i + 3].y * k3.y + q[i + 3].z * k3.z + q[i + 3].w * k3.w;
                }
                float sv = (a0 + a1) + (a2 + a3);
                sv = (jbase + j <= m_global) ? sv : -1e30f;
                s[j] = sv;
                smax = fmaxf(smax, sv);
            }

            float m_new = fmaxf(m_run, smax);
            float corr  = __expf(m_run - m_new);
            l *= corr;
#pragma unroll
            for (int i = 0; i < 16; i++) {
                o[i].x *= corr; o[i].y *= corr; o[i].z *= corr; o[i].w *= corr;
            }
#pragma unroll
            for (int j = 0; j < 16; j++) {
                float p = __expf(s[j] - m_new);
                l += p;
#pragma unroll
                for (int i = 0; i < 16; i++) {
                    float4 vv = Vs[jj + j][i];
                    o[i].x += p * vv.x; o[i].y += p * vv.y;
                    o[i].z += p * vv.z; o[i].w += p * vv.w;
                }
            }
            m_run = m_new;
        }
    }

    float inv = 1.f / l;
    int b = bh >> 4, h = bh & 15;
    float* dst = Og + ((size_t)(b * SEQ + m_global)) * D_MODEL + h * HEAD_DIM;
#pragma unroll
    for (int i = 0; i < 16; i++) {
        float4 ov = o[i];
        ov.x *= inv; ov.y *= inv; ov.z *= inv; ov.w *= inv;
        ((float4*)dst)[i] = ov;
    }
}

// ---------------------------------------------------------------------------
extern "C" void kernel_launch(void* const* d_in, const int* in_sizes, int n_in,
                              void* d_out, int out_size)
{
    (void)in_sizes; (void)n_in; (void)out_size;
    const float* x  = (const float*)d_in[0];
    const float* Wq = (const float*)d_in[1];
    const float* bq = (const float*)d_in[2];
    const float* Wk = (const float*)d_in[3];
    const float* bk = (const float*)d_in[4];
    const float* Wv = (const float*)d_in[5];
    const float* bv = (const float*)d_in[6];
    const float* Wo = (const float*)d_in[7];
    const float* bo = (const float*)d_in[8];
    float* out = (float*)d_out;

    float *gq, *gk, *gv, *gattn;
    cudaGetSymbolAddress((void**)&gq,    g_q);
    cudaGetSymbolAddress((void**)&gk,    g_k);
    cudaGetSymbolAddress((void**)&gv,    g_v);
    cudaGetSymbolAddress((void**)&gattn, g_attn);

    dim3 gemm_grid(D_MODEL / 128, NTOK / 128);   // (8, 32)
    gemm_bias_kernel<1><<<gemm_grid, 256>>>(x, Wq, bq, gq);
    gemm_bias_kernel<1><<<gemm_grid, 256>>>(x, Wk, bk, gk);
    gemm_bias_kernel<1><<<gemm_grid, 256>>>(x, Wv, bv, gv);

    dim3 flash_grid(SEQ / 128, BATCH * NUM_HEADS);  // (16, 32)
    flash_kernel<<<flash_grid, 128>>>(gq, gk, gv, gattn);

    gemm_bias_kernel<0><<<gemm_grid, 256>>>(gattn, Wo, bo, out);
}

// round 5
// speedup vs baseline: 1.3233x; 1.3233x over previous
#include <cuda_runtime.h>
#include <cstdint>

#define D_MODEL   1024
#define NUM_HEADS 16
#define HEAD_DIM  64
#define BATCH     2
#define SEQ       2048
#define NTOK      (BATCH * SEQ)   // 4096

// ---------------------------------------------------------------------------
// Scratch (device globals: no allocation allowed)
// ---------------------------------------------------------------------------
__device__ float g_q[NTOK * D_MODEL];     // [B,H,S,hd]
__device__ float g_k[NTOK * D_MODEL];
__device__ float g_v[NTOK * D_MODEL];
__device__ float g_attn[NTOK * D_MODEL];  // [B,S,D]

__device__ __forceinline__ uint32_t f2tf32(float f) {
    uint32_t r;
    asm("cvt.rna.tf32.f32 %0, %1;" : "=r"(r) : "f"(f));
    return r;
}

__device__ __forceinline__ void mma_tf32(float* d, const uint32_t* a, const uint32_t* b) {
    asm volatile(
        "mma.sync.aligned.m16n8k8.row.col.f32.tf32.tf32.f32 "
        "{%0,%1,%2,%3}, {%4,%5,%6,%7}, {%8,%9}, {%0,%1,%2,%3};"
        : "+f"(d[0]), "+f"(d[1]), "+f"(d[2]), "+f"(d[3])
        : "r"(a[0]), "r"(a[1]), "r"(a[2]), "r"(a[3]), "r"(b[0]), "r"(b[1]));
}

// ---------------------------------------------------------------------------
// tf32 mma.sync GEMM: C[4096,1024] = A[4096,1024] @ W[1024,1024] + bias
// W row-major [K,N] consumed directly (B fragment is k-major x n).
// BM=BN=128, BK=16, 256 threads = 8 warps (2 m x 4 n), warp tile 64x32.
// Double-buffered SMEM, stride 136 floats (conflict-free fragment loads).
// ---------------------------------------------------------------------------
#define BK 16
#define SA 136   // float stride per k-row

template<int SPLIT_HEADS>
__global__ __launch_bounds__(256) void mma_gemm_kernel(
    const float* __restrict__ A,
    const float* __restrict__ W,
    const float* __restrict__ bias,
    float* __restrict__ C)
{
    __shared__ uint32_t As[2][BK * SA];   // As[k][m], m in [0,128)
    __shared__ uint32_t Bs[2][BK * SA];   // Bs[k][n], n in [0,128)

    const int tid  = threadIdx.x;
    const int lane = tid & 31;
    const int wid  = tid >> 5;
    const int warp_m = wid >> 2;          // 0..1  -> 64 rows
    const int warp_n = wid & 3;           // 0..3  -> 32 cols
    const int m0 = blockIdx.y * 128;
    const int n0 = blockIdx.x * 128;

    // global-load mapping
    const int ar  = tid >> 1;             // A row 0..127
    const int akb = (tid & 1) * 8;        // A k-base 0 or 8
    const int bkr = tid >> 4;             // B k-row 0..15
    const int bnb = (tid & 15) * 8;       // B n-base 0..120

    const float* Ag = A + (size_t)(m0 + ar) * D_MODEL + akb;
    const float* Bg = W + (size_t)bkr * D_MODEL + n0 + bnb;

    float4 al0, al1, bl0, bl1;
    auto loadG = [&](int kt) {
        const float* ap = Ag + kt * BK;
        al0 = *(const float4*)(ap);
        al1 = *(const float4*)(ap + 4);
        const float* bp = Bg + (size_t)kt * BK * D_MODEL;
        bl0 = *(const float4*)(bp);
        bl1 = *(const float4*)(bp + 4);
    };
    auto stsTile = [&](int p) {
        uint32_t* as = As[p];
        as[(akb + 0) * SA + ar] = f2tf32(al0.x);
        as[(akb + 1) * SA + ar] = f2tf32(al0.y);
        as[(akb + 2) * SA + ar] = f2tf32(al0.z);
        as[(akb + 3) * SA + ar] = f2tf32(al0.w);
        as[(akb + 4) * SA + ar] = f2tf32(al1.x);
        as[(akb + 5) * SA + ar] = f2tf32(al1.y);
        as[(akb + 6) * SA + ar] = f2tf32(al1.z);
        as[(akb + 7) * SA + ar] = f2tf32(al1.w);
        uint32_t* bs = Bs[p] + bkr * SA + bnb;
        bs[0] = f2tf32(bl0.x); bs[1] = f2tf32(bl0.y);
        bs[2] = f2tf32(bl0.z); bs[3] = f2tf32(bl0.w);
        bs[4] = f2tf32(bl1.x); bs[5] = f2tf32(bl1.y);
        bs[6] = f2tf32(bl1.z); bs[7] = f2tf32(bl1.w);
    };

    float acc[4][4][4];
#pragma unroll
    for (int i = 0; i < 4; i++)
#pragma unroll
        for (int j = 0; j < 4; j++)
#pragma unroll
            for (int r = 0; r < 4; r++) acc[i][j][r] = 0.f;

    loadG(0);
    stsTile(0);
    __syncthreads();

    const int r0 = warp_m * 64 + (lane >> 2);
    const int nb = warp_n * 32 + (lane >> 2);
    const int kq = lane & 3;

    int p = 0;
    for (int kt = 0; kt < D_MODEL / BK; kt++) {
        if (kt < D_MODEL / BK - 1) loadG(kt + 1);

        const uint32_t* as = As[p];
        const uint32_t* bs = Bs[p];
#pragma unroll
        for (int k8 = 0; k8 < BK; k8 += 8) {
            const int kk = k8 + kq;
            uint32_t a[4][4], b[4][2];
#pragma unroll
            for (int mt = 0; mt < 4; mt++) {
                a[mt][0] = as[kk * SA + r0 + mt * 16];
                a[mt][1] = as[kk * SA + r0 + mt * 16 + 8];
                a[mt][2] = as[(kk + 4) * SA + r0 + mt * 16];
                a[mt][3] = as[(kk + 4) * SA + r0 + mt * 16 + 8];
            }
#pragma unroll
            for (int nt = 0; nt < 4; nt++) {
                b[nt][0] = bs[kk * SA + nb + nt * 8];
                b[nt][1] = bs[(kk + 4) * SA + nb + nt * 8];
            }
#pragma unroll
            for (int mt = 0; mt < 4; mt++)
#pragma unroll
                for (int nt = 0; nt < 4; nt++)
                    mma_tf32(acc[mt][nt], a[mt], b[nt]);
        }

        if (kt < D_MODEL / BK - 1) {
            stsTile(p ^ 1);
            __syncthreads();
        }
        p ^= 1;
    }

    // epilogue: c0/c1 at (row, col..col+1), c2/c3 at (row+8, col..col+1)
#pragma unroll
    for (int mt = 0; mt < 4; mt++) {
        const int gm_lo = m0 + warp_m * 64 + mt * 16 + (lane >> 2);
#pragma unroll
        for (int nt = 0; nt < 4; nt++) {
            const int gn = n0 + warp_n * 32 + nt * 8 + (lane & 3) * 2;
            const float2 bv = *(const float2*)(bias + gn);
            float2 v0 = make_float2(acc[mt][nt][0] + bv.x, acc[mt][nt][1] + bv.y);
            float2 v1 = make_float2(acc[mt][nt][2] + bv.x, acc[mt][nt][3] + bv.y);
            if (SPLIT_HEADS) {
                const int h = gn >> 6, dh = gn & (HEAD_DIM - 1);
                {
                    const int b = gm_lo >> 11, s = gm_lo & (SEQ - 1);
                    *(float2*)(C + (((size_t)(b * NUM_HEADS + h) * SEQ + s) * HEAD_DIM + dh)) = v0;
                }
                {
                    const int gm = gm_lo + 8;
                    const int b = gm >> 11, s = gm & (SEQ - 1);
                    *(float2*)(C + (((size_t)(b * NUM_HEADS + h) * SEQ + s) * HEAD_DIM + dh)) = v1;
                }
            } else {
                *(float2*)(C + (size_t)gm_lo * D_MODEL + gn) = v0;
                *(float2*)(C + (size_t)(gm_lo + 8) * D_MODEL + gn) = v1;
            }
        }
    }
}

// ---------------------------------------------------------------------------
// Flash attention (fp32, causal). 1 thread = 1 query row, 256 threads/block.
// ---------------------------------------------------------------------------
#define FTILE 64
#define QROWS 256

__global__ __launch_bounds__(QROWS, 1) void flash_kernel(
    const float* __restrict__ Q,
    const float* __restrict__ Kg,
    const float* __restrict__ Vg,
    float* __restrict__ Og)
{
    __shared__ float4 Ks[FTILE][16];
    __shared__ float4 Vs[FTILE][16];

    const int bh  = blockIdx.y;
    const int qt  = (int)gridDim.x - 1 - (int)blockIdx.x;   // heavy tiles first
    const int tid = threadIdx.x;
    const int m_global = qt * QROWS + tid;

    const float* qptr = Q + ((size_t)bh * SEQ + m_global) * HEAD_DIM;
    const float* kb   = Kg + (size_t)bh * SEQ * HEAD_DIM;
    const float* vb   = Vg + (size_t)bh * SEQ * HEAD_DIM;

    const float scale = 0.125f;
    float4 q[16];
#pragma unroll
    for (int i = 0; i < 16; i++) {
        q[i] = ((const float4*)qptr)[i];
        q[i].x *= scale; q[i].y *= scale; q[i].z *= scale; q[i].w *= scale;
    }

    float4 o[16];
#pragma unroll
    for (int i = 0; i < 16; i++) o[i] = make_float4(0.f, 0.f, 0.f, 0.f);
    float m_run = -1e30f, l = 0.f;

    const int kv_end = qt * QROWS + QROWS;
    for (int j0 = 0; j0 < kv_end; j0 += FTILE) {
        __syncthreads();
#pragma unroll
        for (int r = 0; r < 4; r++) {
            int idx = tid + r * QROWS;    // 0..1023
            int rw  = idx >> 4;
            int c   = idx & 15;
            Ks[rw][c] = ((const float4*)(kb + (size_t)(j0 + rw) * HEAD_DIM))[c];
            Vs[rw][c] = ((const float4*)(vb + (size_t)(j0 + rw) * HEAD_DIM))[c];
        }
        __syncthreads();

#pragma unroll 1
        for (int jj = 0; jj < FTILE; jj += 16) {
            int jbase = j0 + jj;
            if (jbase > m_global) break;

            float s[16];
            float smax = -1e30f;
#pragma unroll
            for (int j = 0; j < 16; j++) {
                float a0 = 0.f, a1 = 0.f, a2 = 0.f, a3 = 0.f;
#pragma unroll
                for (int i = 0; i < 16; i += 4) {
                    float4 k0 = Ks[jj + j][i + 0];
                    float4 k1 = Ks[jj + j][i + 1];
                    float4 k2 = Ks[jj + j][i + 2];
                    float4 k3 = Ks[jj + j][i + 3];
                    a0 += q[i + 0].x * k0.x + q[i + 0].y * k0.y + q[i + 0].z * k0.z + q[i + 0].w * k0.w;
                    a1 += q[i + 1].x * k1.x + q[i + 1].y * k1.y + q[i + 1].z * k1.z + q[i + 1].w * k1.w;
                    a2 += q[i + 2].x * k2.x + q[i + 2].y * k2.y + q[i + 2].z * k2.z + q[i + 2].w * k2.w;
                    a3 += q[i + 3].x * k3.x + q[i + 3].y * k3.y + q[i + 3].z * k3.z + q[i + 3].w * k3.w;
                }
                float sv = (a0 + a1) + (a2 + a3);
                sv = (jbase + j <= m_global) ? sv : -1e30f;
                s[j] = sv;
                smax = fmaxf(smax, sv);
            }

            float m_new = fmaxf(m_run, smax);
            float corr  = __expf(m_run - m_new);
            l *= corr;
#pragma unroll
            for (int i = 0; i < 16; i++) {
                o[i].x *= corr; o[i].y *= corr; o[i].z *= corr; o[i].w *= corr;
            }
#pragma unroll
            for (int j = 0; j < 16; j++) {
                float p = __expf(s[j] - m_new);
                l += p;
#pragma unroll
                for (int i = 0; i < 16; i++) {
                    float4 vv = Vs[jj + j][i];
                    o[i].x += p * vv.x; o[i].y += p * vv.y;
                    o[i].z += p * vv.z; o[i].w += p * vv.w;
                }
            }
            m_run = m_new;
        }
    }

    float inv = 1.f / l;
    int b = bh >> 4, h = bh & 15;
    float* dst = Og + ((size_t)(b * SEQ + m_global)) * D_MODEL + h * HEAD_DIM;
#pragma unroll
    for (int i = 0; i < 16; i++) {
        float4 ov = o[i];
        ov.x *= inv; ov.y *= inv; ov.z *= inv; ov.w *= inv;
        ((float4*)dst)[i] = ov;
    }
}

// ---------------------------------------------------------------------------
extern "C" void kernel_launch(void* const* d_in, const int* in_sizes, int n_in,
                              void* d_out, int out_size)
{
    (void)in_sizes; (void)n_in; (void)out_size;
    const float* x  = (const float*)d_in[0];
    const float* Wq = (const float*)d_in[1];
    const float* bq = (const float*)d_in[2];
    const float* Wk = (const float*)d_in[3];
    const float* bk = (const float*)d_in[4];
    const float* Wv = (const float*)d_in[5];
    const float* bv = (const float*)d_in[6];
    const float* Wo = (const float*)d_in[7];
    const float* bo = (const float*)d_in[8];
    float* out = (float*)d_out;

    float *gq, *gk, *gv, *gattn;
    cudaGetSymbolAddress((void**)&gq,    g_q);
    cudaGetSymbolAddress((void**)&gk,    g_k);
    cudaGetSymbolAddress((void**)&gv,    g_v);
    cudaGetSymbolAddress((void**)&gattn, g_attn);

    dim3 gemm_grid(D_MODEL / 128, NTOK / 128);   // (8, 32)
    mma_gemm_kernel<1><<<gemm_grid, 256>>>(x, Wq, bq, gq);
    mma_gemm_kernel<1><<<gemm_grid, 256>>>(x, Wk, bk, gk);
    mma_gemm_kernel<1><<<gemm_grid, 256>>>(x, Wv, bv, gv);

    dim3 flash_grid(SEQ / QROWS, BATCH * NUM_HEADS);  // (8, 32)
    flash_kernel<<<flash_grid, QROWS>>>(gq, gk, gv, gattn);

    mma_gemm_kernel<0><<<gemm_grid, 256>>>(gattn, Wo, bo, out);
}

// round 7
// speedup vs baseline: 3.0880x; 2.3336x over previous
#include <cuda_runtime.h>
#include <cstdint>

#define D_MODEL   1024
#define NUM_HEADS 16
#define HEAD_DIM  64
#define BATCH     2
#define SEQ       2048
#define NTOK      (BATCH * SEQ)   // 4096

// ---------------------------------------------------------------------------
// Scratch (device globals: no allocation allowed)
// ---------------------------------------------------------------------------
__device__ float g_q[NTOK * D_MODEL];     // [B,H,S,hd]
__device__ float g_k[NTOK * D_MODEL];
__device__ float g_v[NTOK * D_MODEL];
__device__ float g_attn[NTOK * D_MODEL];  // [B,S,D]

__device__ __forceinline__ uint32_t f2tf32(float f) {
    uint32_t r;
    asm("cvt.rna.tf32.f32 %0, %1;" : "=r"(r) : "f"(f));
    return r;
}

__device__ __forceinline__ void mma_tf32(float* d, const uint32_t* a, const uint32_t* b) {
    asm volatile(
        "mma.sync.aligned.m16n8k8.row.col.f32.tf32.tf32.f32 "
        "{%0,%1,%2,%3}, {%4,%5,%6,%7}, {%8,%9}, {%0,%1,%2,%3};"
        : "+f"(d[0]), "+f"(d[1]), "+f"(d[2]), "+f"(d[3])
        : "r"(a[0]), "r"(a[1]), "r"(a[2]), "r"(a[3]), "r"(b[0]), "r"(b[1]));
}

// ---------------------------------------------------------------------------
// tf32 mma.sync GEMM (unchanged from R5 passing kernel)
// ---------------------------------------------------------------------------
#define BK 16
#define SA 136   // float stride per k-row

template<int SPLIT_HEADS>
__global__ __launch_bounds__(256) void mma_gemm_kernel(
    const float* __restrict__ A,
    const float* __restrict__ W,
    const float* __restrict__ bias,
    float* __restrict__ C)
{
    __shared__ uint32_t As[2][BK * SA];   // As[k][m]
    __shared__ uint32_t Bs[2][BK * SA];   // Bs[k][n]

    const int tid  = threadIdx.x;
    const int lane = tid & 31;
    const int wid  = tid >> 5;
    const int warp_m = wid >> 2;
    const int warp_n = wid & 3;
    const int m0 = blockIdx.y * 128;
    const int n0 = blockIdx.x * 128;

    const int ar  = tid >> 1;
    const int akb = (tid & 1) * 8;
    const int bkr = tid >> 4;
    const int bnb = (tid & 15) * 8;

    const float* Ag = A + (size_t)(m0 + ar) * D_MODEL + akb;
    const float* Bg = W + (size_t)bkr * D_MODEL + n0 + bnb;

    float4 al0, al1, bl0, bl1;
    auto loadG = [&](int kt) {
        const float* ap = Ag + kt * BK;
        al0 = *(const float4*)(ap);
        al1 = *(const float4*)(ap + 4);
        const float* bp = Bg + (size_t)kt * BK * D_MODEL;
        bl0 = *(const float4*)(bp);
        bl1 = *(const float4*)(bp + 4);
    };
    auto stsTile = [&](int p) {
        uint32_t* as = As[p];
        as[(akb + 0) * SA + ar] = f2tf32(al0.x);
        as[(akb + 1) * SA + ar] = f2tf32(al0.y);
        as[(akb + 2) * SA + ar] = f2tf32(al0.z);
        as[(akb + 3) * SA + ar] = f2tf32(al0.w);
        as[(akb + 4) * SA + ar] = f2tf32(al1.x);
        as[(akb + 5) * SA + ar] = f2tf32(al1.y);
        as[(akb + 6) * SA + ar] = f2tf32(al1.z);
        as[(akb + 7) * SA + ar] = f2tf32(al1.w);
        uint32_t* bs = Bs[p] + bkr * SA + bnb;
        bs[0] = f2tf32(bl0.x); bs[1] = f2tf32(bl0.y);
        bs[2] = f2tf32(bl0.z); bs[3] = f2tf32(bl0.w);
        bs[4] = f2tf32(bl1.x); bs[5] = f2tf32(bl1.y);
        bs[6] = f2tf32(bl1.z); bs[7] = f2tf32(bl1.w);
    };

    float acc[4][4][4];
#pragma unroll
    for (int i = 0; i < 4; i++)
#pragma unroll
        for (int j = 0; j < 4; j++)
#pragma unroll
            for (int r = 0; r < 4; r++) acc[i][j][r] = 0.f;

    loadG(0);
    stsTile(0);
    __syncthreads();

    const int r0 = warp_m * 64 + (lane >> 2);
    const int nb = warp_n * 32 + (lane >> 2);
    const int kq = lane & 3;

    int p = 0;
    for (int kt = 0; kt < D_MODEL / BK; kt++) {
        if (kt < D_MODEL / BK - 1) loadG(kt + 1);

        const uint32_t* as = As[p];
        const uint32_t* bs = Bs[p];
#pragma unroll
        for (int k8 = 0; k8 < BK; k8 += 8) {
            const int kk = k8 + kq;
            uint32_t a[4][4], b[4][2];
#pragma unroll
            for (int mt = 0; mt < 4; mt++) {
                a[mt][0] = as[kk * SA + r0 + mt * 16];
                a[mt][1] = as[kk * SA + r0 + mt * 16 + 8];
                a[mt][2] = as[(kk + 4) * SA + r0 + mt * 16];
                a[mt][3] = as[(kk + 4) * SA + r0 + mt * 16 + 8];
            }
#pragma unroll
            for (int nt = 0; nt < 4; nt++) {
                b[nt][0] = bs[kk * SA + nb + nt * 8];
                b[nt][1] = bs[(kk + 4) * SA + nb + nt * 8];
            }
#pragma unroll
            for (int mt = 0; mt < 4; mt++)
#pragma unroll
                for (int nt = 0; nt < 4; nt++)
                    mma_tf32(acc[mt][nt], a[mt], b[nt]);
        }

        if (kt < D_MODEL / BK - 1) {
            stsTile(p ^ 1);
            __syncthreads();
        }
        p ^= 1;
    }

#pragma unroll
    for (int mt = 0; mt < 4; mt++) {
        const int gm_lo = m0 + warp_m * 64 + mt * 16 + (lane >> 2);
#pragma unroll
        for (int nt = 0; nt < 4; nt++) {
            const int gn = n0 + warp_n * 32 + nt * 8 + (lane & 3) * 2;
            const float2 bv = *(const float2*)(bias + gn);
            float2 v0 = make_float2(acc[mt][nt][0] + bv.x, acc[mt][nt][1] + bv.y);
            float2 v1 = make_float2(acc[mt][nt][2] + bv.x, acc[mt][nt][3] + bv.y);
            if (SPLIT_HEADS) {
                const int h = gn >> 6, dh = gn & (HEAD_DIM - 1);
                {
                    const int b = gm_lo >> 11, s = gm_lo & (SEQ - 1);
                    *(float2*)(C + (((size_t)(b * NUM_HEADS + h) * SEQ + s) * HEAD_DIM + dh)) = v0;
                }
                {
                    const int gm = gm_lo + 8;
                    const int b = gm >> 11, s = gm & (SEQ - 1);
                    *(float2*)(C + (((size_t)(b * NUM_HEADS + h) * SEQ + s) * HEAD_DIM + dh)) = v1;
                }
            } else {
                *(float2*)(C + (size_t)gm_lo * D_MODEL + gn) = v0;
                *(float2*)(C + (size_t)(gm_lo + 8) * D_MODEL + gn) = v1;
            }
        }
    }
}

// ---------------------------------------------------------------------------
// Tensor-core flash attention (tf32 mma.sync, causal).
// Block = 128 q rows x 1 (b,h). 8 warps, 16 rows each. KV tile = 64 keys.
// QK^T: Q split big+small tf32 (2 compensated mmas), K pre-rounded tf32.
// PV:   P tf32 (via quad shuffles from score accum), V pre-rounded tf32.
// ---------------------------------------------------------------------------
#define BQ  128
#define BKV 64
#define KST 68    // float stride: conflict-free fragment loads

__global__ __launch_bounds__(256, 1) void flash_tc_kernel(
    const float* __restrict__ Qg,
    const float* __restrict__ Kg,
    const float* __restrict__ Vg,
    float* __restrict__ Og)
{
    __shared__ float Ks[BKV * KST];
    __shared__ float Vs[BKV * KST];

    const int bh   = blockIdx.y;
    const int qt   = (int)gridDim.x - 1 - (int)blockIdx.x;  // heavy tiles first
    const int tid  = threadIdx.x;
    const int lane = tid & 31;
    const int wid  = tid >> 5;
    const int g    = lane >> 2;       // 0..7
    const int qd   = lane & 3;        // 0..3
    const int q0   = qt * BQ;
    const int rw   = q0 + wid * 16;   // warp's first q row

    // ---- load Q fragments (scaled), split into big + small tf32 ----
    uint32_t qbig[8][4], qsml[8][4];
    {
        const float* qb = Qg + ((size_t)bh * SEQ + rw) * HEAD_DIM;
#pragma unroll
        for (int ks = 0; ks < 8; ks++) {
            const int d0 = ks * 8 + qd;
            float v[4];
            v[0] = qb[(size_t)g * HEAD_DIM + d0] * 0.125f;
            v[1] = qb[(size_t)(g + 8) * HEAD_DIM + d0] * 0.125f;
            v[2] = qb[(size_t)g * HEAD_DIM + d0 + 4] * 0.125f;
            v[3] = qb[(size_t)(g + 8) * HEAD_DIM + d0 + 4] * 0.125f;
#pragma unroll
            for (int r = 0; r < 4; r++) {
                uint32_t big = f2tf32(v[r]);
                qbig[ks][r] = big;
                qsml[ks][r] = f2tf32(v[r] - __uint_as_float(big));
            }
        }
    }

    float o[8][4];
#pragma unroll
    for (int nt = 0; nt < 8; nt++)
#pragma unroll
        for (int r = 0; r < 4; r++) o[nt][r] = 0.f;
    float m0 = -1e30f, m1 = -1e30f, l0 = 0.f, l1 = 0.f;

    const float* kbase = Kg + (size_t)bh * SEQ * HEAD_DIM;
    const float* vbase = Vg + (size_t)bh * SEQ * HEAD_DIM;

    const int kv_end = q0 + BQ;
    for (int j0 = 0; j0 < kv_end; j0 += BKV) {
        __syncthreads();
        // load K/V tile, pre-rounded to tf32 (rna)
#pragma unroll
        for (int t = 0; t < 4; t++) {
            const int v4  = tid + t * 256;      // 0..1023
            const int row = v4 >> 4;
            const int c   = (v4 & 15) * 4;
            float4 kk4 = *(const float4*)(kbase + (size_t)(j0 + row) * HEAD_DIM + c);
            float4 vv4 = *(const float4*)(vbase + (size_t)(j0 + row) * HEAD_DIM + c);
            float* kd = &Ks[row * KST + c];
            kd[0] = __uint_as_float(f2tf32(kk4.x));
            kd[1] = __uint_as_float(f2tf32(kk4.y));
            kd[2] = __uint_as_float(f2tf32(kk4.z));
            kd[3] = __uint_as_float(f2tf32(kk4.w));
            float* vd = &Vs[row * KST + c];
            vd[0] = __uint_as_float(f2tf32(vv4.x));
            vd[1] = __uint_as_float(f2tf32(vv4.y));
            vd[2] = __uint_as_float(f2tf32(vv4.z));
            vd[3] = __uint_as_float(f2tf32(vv4.w));
        }
        __syncthreads();
        if (j0 > rw + 15) continue;   // fully masked for this warp

        // ---- S = (Q/8) K^T  (2-mma compensated) ----
        float sacc[8][4];
#pragma unroll
        for (int nt = 0; nt < 8; nt++)
#pragma unroll
            for (int r = 0; r < 4; r++) sacc[nt][r] = 0.f;

#pragma unroll
        for (int ks = 0; ks < 8; ks++) {
#pragma unroll
            for (int nt = 0; nt < 8; nt++) {
                uint32_t b[2];
                b[0] = __float_as_uint(Ks[(nt * 8 + g) * KST + ks * 8 + qd]);
                b[1] = __float_as_uint(Ks[(nt * 8 + g) * KST + ks * 8 + qd + 4]);
                mma_tf32(sacc[nt], qbig[ks], b);
                mma_tf32(sacc[nt], qsml[ks], b);
            }
        }

        // ---- causal mask (diagonal tiles only) ----
        if (j0 + BKV - 1 > rw) {
            const int rlo = rw + g, rhi = rlo + 8;
#pragma unroll
            for (int nt = 0; nt < 8; nt++) {
                const int col = j0 + nt * 8 + 2 * qd;
                if (col     > rlo) sacc[nt][0] = -1e30f;
                if (col + 1 > rlo) sacc[nt][1] = -1e30f;
                if (col     > rhi) sacc[nt][2] = -1e30f;
                if (col + 1 > rhi) sacc[nt][3] = -1e30f;
            }
        }

        // ---- online softmax ----
        float rmax0 = -1e30f, rmax1 = -1e30f;
#pragma unroll
        for (int nt = 0; nt < 8; nt++) {
            rmax0 = fmaxf(rmax0, fmaxf(sacc[nt][0], sacc[nt][1]));
            rmax1 = fmaxf(rmax1, fmaxf(sacc[nt][2], sacc[nt][3]));
        }
        rmax0 = fmaxf(rmax0, __shfl_xor_sync(0xffffffffu, rmax0, 1));
        rmax0 = fmaxf(rmax0, __shfl_xor_sync(0xffffffffu, rmax0, 2));
        rmax1 = fmaxf(rmax1, __shfl_xor_sync(0xffffffffu, rmax1, 1));
        rmax1 = fmaxf(rmax1, __shfl_xor_sync(0xffffffffu, rmax1, 2));

        const float mn0 = fmaxf(m0, rmax0);
        const float mn1 = fmaxf(m1, rmax1);
        const float corr0 = __expf(m0 - mn0);
        const float corr1 = __expf(m1 - mn1);
        m0 = mn0; m1 = mn1;
        l0 *= corr0; l1 *= corr1;
#pragma unroll
        for (int nt = 0; nt < 8; nt++) {
            o[nt][0] *= corr0; o[nt][1] *= corr0;
            o[nt][2] *= corr1; o[nt][3] *= corr1;
        }
#pragma unroll
        for (int nt = 0; nt < 8; nt++) {
            float p0 = __expf(sacc[nt][0] - mn0);
            float p1 = __expf(sacc[nt][1] - mn0);
            float p2 = __expf(sacc[nt][2] - mn1);
            float p3 = __expf(sacc[nt][3] - mn1);
            l0 += p0 + p1; l1 += p2 + p3;
            sacc[nt][0] = p0; sacc[nt][1] = p1;
            sacc[nt][2] = p2; sacc[nt][3] = p3;
        }

        // ---- O += P V : build P A-frags via quad shuffles ----
        const int srcA = (g << 2) | (qd >> 1);
        const int srcB = srcA + 2;
#pragma unroll
        for (int kt = 0; kt < 8; kt++) {
            float x0 = __shfl_sync(0xffffffffu, sacc[kt][0], srcA);
            float x1 = __shfl_sync(0xffffffffu, sacc[kt][1], srcA);
            float x2 = __shfl_sync(0xffffffffu, sacc[kt][2], srcA);
            float x3 = __shfl_sync(0xffffffffu, sacc[kt][3], srcA);
            float y0 = __shfl_sync(0xffffffffu, sacc[kt][0], srcB);
            float y1 = __shfl_sync(0xffffffffu, sacc[kt][1], srcB);
            float y2 = __shfl_sync(0xffffffffu, sacc[kt][2], srcB);
            float y3 = __shfl_sync(0xffffffffu, sacc[kt][3], srcB);
            uint32_t pa[4];
            pa[0] = f2tf32((qd & 1) ? x1 : x0);
            pa[1] = f2tf32((qd & 1) ? x3 : x2);
            pa[2] = f2tf32((qd & 1) ? y1 : y0);
            pa[3] = f2tf32((qd & 1) ? y3 : y2);
#pragma unroll
            for (int nt = 0; nt < 8; nt++) {
                uint32_t b[2];
                b[0] = __float_as_uint(Vs[(kt * 8 + qd) * KST + nt * 8 + g]);
                b[1] = __float_as_uint(Vs[(kt * 8 + qd + 4) * KST + nt * 8 + g]);
                mma_tf32(o[nt], pa, b);
            }
        }
    }

    // ---- finalize: reduce l over quad, normalize, write [B,S,D] ----
    l0 += __shfl_xor_sync(0xffffffffu, l0, 1);
    l0 += __shfl_xor_sync(0xffffffffu, l0, 2);
    l1 += __shfl_xor_sync(0xffffffffu, l1, 1);
    l1 += __shfl_xor_sync(0xffffffffu, l1, 2);
    const float inv0 = 1.f / l0;
    const float inv1 = 1.f / l1;

    const int b = bh >> 4, h = bh & 15;
    const int row_lo = rw + g;
    float* dlo = Og + ((size_t)(b * SEQ + row_lo)) * D_MODEL + h * HEAD_DIM + 2 * qd;
    float* dhi = Og + ((size_t)(b * SEQ + row_lo + 8)) * D_MODEL + h * HEAD_DIM + 2 * qd;
#pragma unroll
    for (int nt = 0; nt < 8; nt++) {
        *(float2*)(dlo + nt * 8) = make_float2(o[nt][0] * inv0, o[nt][1] * inv0);
        *(float2*)(dhi + nt * 8) = make_float2(o[nt][2] * inv1, o[nt][3] * inv1);
    }
}

// ---------------------------------------------------------------------------
extern "C" void kernel_launch(void* const* d_in, const int* in_sizes, int n_in,
                              void* d_out, int out_size)
{
    (void)in_sizes; (void)n_in; (void)out_size;
    const float* x  = (const float*)d_in[0];
    const float* Wq = (const float*)d_in[1];
    const float* bq = (const float*)d_in[2];
    const float* Wk = (const float*)d_in[3];
    const float* bk = (const float*)d_in[4];
    const float* Wv = (const float*)d_in[5];
    const float* bv = (const float*)d_in[6];
    const float* Wo = (const float*)d_in[7];
    const float* bo = (const float*)d_in[8];
    float* out = (float*)d_out;

    float *gq, *gk, *gv, *gattn;
    cudaGetSymbolAddress((void**)&gq,    g_q);
    cudaGetSymbolAddress((void**)&gk,    g_k);
    cudaGetSymbolAddress((void**)&gv,    g_v);
    cudaGetSymbolAddress((void**)&gattn, g_attn);

    dim3 gemm_grid(D_MODEL / 128, NTOK / 128);   // (8, 32)
    mma_gemm_kernel<1><<<gemm_grid, 256>>>(x, Wq, bq, gq);
    mma_gemm_kernel<1><<<gemm_grid, 256>>>(x, Wk, bk, gk);
    mma_gemm_kernel<1><<<gemm_grid, 256>>>(x, Wv, bv, gv);

    dim3 flash_grid(SEQ / BQ, BATCH * NUM_HEADS);  // (16, 32)
    flash_tc_kernel<<<flash_grid, 256>>>(gq, gk, gv, gattn);

    mma_gemm_kernel<0><<<gemm_grid, 256>>>(gattn, Wo, bo, out);
}

// round 8
// speedup vs baseline: 3.2844x; 1.0636x over previous
#include <cuda_runtime.h>
#include <cstdint>

#define D_MODEL   1024
#define NUM_HEADS 16
#define HEAD_DIM  64
#define BATCH     2
#define SEQ       2048
#define NTOK      (BATCH * SEQ)   // 4096

// ---------------------------------------------------------------------------
// Scratch (device globals: no allocation allowed)
// ---------------------------------------------------------------------------
__device__ float g_q[NTOK * D_MODEL];     // [B,H,S,hd] full fp32 (compensation)
__device__ float g_k[NTOK * D_MODEL];     // [B,H,S,hd] tf32-rounded
__device__ float g_v[NTOK * D_MODEL];     // [B,H,S,hd] tf32-rounded
__device__ float g_attn[NTOK * D_MODEL];  // [B,S,D]    tf32-rounded
__device__ float g_xt[NTOK * D_MODEL];    // x tf32-rounded
__device__ float g_wq[D_MODEL * D_MODEL]; // W tf32-rounded
__device__ float g_wk[D_MODEL * D_MODEL];
__device__ float g_wv[D_MODEL * D_MODEL];
__device__ float g_wo[D_MODEL * D_MODEL];

__device__ __forceinline__ uint32_t f2tf32(float f) {
    uint32_t r;
    asm("cvt.rna.tf32.f32 %0, %1;" : "=r"(r) : "f"(f));
    return r;
}
__device__ __forceinline__ void mma_tf32(float* d, const uint32_t* a, const uint32_t* b) {
    asm volatile(
        "mma.sync.aligned.m16n8k8.row.col.f32.tf32.tf32.f32 "
        "{%0,%1,%2,%3}, {%4,%5,%6,%7}, {%8,%9}, {%0,%1,%2,%3};"
        : "+f"(d[0]), "+f"(d[1]), "+f"(d[2]), "+f"(d[3])
        : "r"(a[0]), "r"(a[1]), "r"(a[2]), "r"(a[3]), "r"(b[0]), "r"(b[1]));
}
__device__ __forceinline__ void cp16(uint32_t s, const void* g) {
    asm volatile("cp.async.cg.shared.global [%0], [%1], 16;" :: "r"(s), "l"(g) : "memory");
}
#define CP_COMMIT() asm volatile("cp.async.commit_group;" ::: "memory")
template<int N> __device__ __forceinline__ void cp_wait() {
    asm volatile("cp.async.wait_group %0;" :: "n"(N) : "memory");
}
__device__ __forceinline__ uint32_t smem_u32(const void* p) {
    uint32_t a;
    asm("{ .reg .u64 t; cvta.to.shared.u64 t, %1; cvt.u32.u64 %0, t; }" : "=r"(a) : "l"(p));
    return a;
}

// ---------------------------------------------------------------------------
// Elementwise tf32 pre-round
// ---------------------------------------------------------------------------
__global__ __launch_bounds__(256) void round_tf32_kernel(
    const float* __restrict__ in, float* __restrict__ out)
{
    const int i = (blockIdx.x * 256 + threadIdx.x) * 4;
    float4 v = *(const float4*)(in + i);
    v.x = __uint_as_float(f2tf32(v.x));
    v.y = __uint_as_float(f2tf32(v.y));
    v.z = __uint_as_float(f2tf32(v.z));
    v.w = __uint_as_float(f2tf32(v.w));
    *(float4*)(out + i) = v;
}

// ---------------------------------------------------------------------------
// GEMM v2: C[4096,1024] = A @ W + bias.  A,W already tf32-rounded fp32.
// 128x128 tile, BK=16, 8 warps (2x4), warp 64x32, cp.async 4-stage pipeline.
// A smem [m][k] stride 20 (conflict-free frags), B smem [k][n] stride 136.
// ---------------------------------------------------------------------------
#define NST  4
#define ASTR 20
#define BSTR 136
#define A_ST_BYTES (128 * ASTR * 4)               // 10240
#define B_ST_BYTES (16 * BSTR * 4)                // 8704
#define G_STAGE    (A_ST_BYTES + B_ST_BYTES)      // 18944
#define GEMM_SMEM  (NST * G_STAGE)                // 75776

template<int SPLIT_HEADS, int ROUND_OUT>
__global__ __launch_bounds__(256, 2) void mma_gemm2(
    const float* __restrict__ A,
    const float* __restrict__ W,
    const float* __restrict__ bias,
    float* __restrict__ C)
{
    extern __shared__ char sm[];
    const uint32_t sbase = smem_u32(sm);

    const int tid  = threadIdx.x;
    const int lane = tid & 31;
    const int wid  = tid >> 5;
    const int warp_m = wid >> 2;
    const int warp_n = wid & 3;
    const int m0 = blockIdx.y * 128;
    const int n0 = blockIdx.x * 128;

    // copy mapping (2 A-chunks + 2 B-chunks of 16B per thread per stage)
    const int ca  = tid * 2;
    const int am  = ca >> 2, akc = ca & 3;          // A: row, k-chunk (even)
    const int bkr = ca >> 5, bnc = ca & 31;         // B: k-row, n-chunk (even)

    auto issue = [&](int kt) {
        const int s = kt & (NST - 1);
        const uint32_t sa = sbase + s * G_STAGE;
        const uint32_t sb = sa + A_ST_BYTES;
        const int k0 = kt * 16;
        const float* ga = A + (size_t)(m0 + am) * D_MODEL + k0 + akc * 4;
        cp16(sa + (am * ASTR + akc * 4) * 4, ga);
        cp16(sa + (am * ASTR + (akc + 1) * 4) * 4, ga + 4);
        const float* gb = W + (size_t)(k0 + bkr) * D_MODEL + n0 + bnc * 4;
        cp16(sb + (bkr * BSTR + bnc * 4) * 4, gb);
        cp16(sb + (bkr * BSTR + (bnc + 1) * 4) * 4, gb + 4);
        CP_COMMIT();
    };

    float acc[4][4][4];
#pragma unroll
    for (int i = 0; i < 4; i++)
#pragma unroll
        for (int j = 0; j < 4; j++)
#pragma unroll
            for (int r = 0; r < 4; r++) acc[i][j][r] = 0.f;

    issue(0); issue(1); issue(2);

    const int g  = lane >> 2;
    const int qd = lane & 3;
    const int ar0 = warp_m * 64 + g;
    const int nb  = warp_n * 32 + g;

    for (int kt = 0; kt < D_MODEL / 16; kt++) {
        const int st = kt & (NST - 1);
        cp_wait<2>();
        __syncthreads();
        if (kt + 3 < D_MODEL / 16) issue(kt + 3); else CP_COMMIT();

        const uint32_t* as = (const uint32_t*)(sm + st * G_STAGE);
        const uint32_t* bs = (const uint32_t*)(sm + st * G_STAGE + A_ST_BYTES);
#pragma unroll
        for (int k8 = 0; k8 < 16; k8 += 8) {
            const int kk = k8 + qd;
            uint32_t a[4][4], b[4][2];
#pragma unroll
            for (int mt = 0; mt < 4; mt++) {
                const int r = ar0 + mt * 16;
                a[mt][0] = as[r * ASTR + kk];
                a[mt][1] = as[(r + 8) * ASTR + kk];
                a[mt][2] = as[r * ASTR + kk + 4];
                a[mt][3] = as[(r + 8) * ASTR + kk + 4];
            }
#pragma unroll
            for (int nt = 0; nt < 4; nt++) {
                b[nt][0] = bs[kk * BSTR + nb + nt * 8];
                b[nt][1] = bs[(kk + 4) * BSTR + nb + nt * 8];
            }
#pragma unroll
            for (int mt = 0; mt < 4; mt++)
#pragma unroll
                for (int nt = 0; nt < 4; nt++)
                    mma_tf32(acc[mt][nt], a[mt], b[nt]);
        }
    }

#pragma unroll
    for (int mt = 0; mt < 4; mt++) {
        const int gm_lo = m0 + warp_m * 64 + mt * 16 + g;
#pragma unroll
        for (int nt = 0; nt < 4; nt++) {
            const int gn = n0 + warp_n * 32 + nt * 8 + qd * 2;
            const float2 bv = *(const float2*)(bias + gn);
            float2 v0 = make_float2(acc[mt][nt][0] + bv.x, acc[mt][nt][1] + bv.y);
            float2 v1 = make_float2(acc[mt][nt][2] + bv.x, acc[mt][nt][3] + bv.y);
            if (ROUND_OUT) {
                v0.x = __uint_as_float(f2tf32(v0.x));
                v0.y = __uint_as_float(f2tf32(v0.y));
                v1.x = __uint_as_float(f2tf32(v1.x));
                v1.y = __uint_as_float(f2tf32(v1.y));
            }
            if (SPLIT_HEADS) {
                const int h = gn >> 6, dh = gn & (HEAD_DIM - 1);
                {
                    const int b = gm_lo >> 11, s = gm_lo & (SEQ - 1);
                    *(float2*)(C + (((size_t)(b * NUM_HEADS + h) * SEQ + s) * HEAD_DIM + dh)) = v0;
                }
                {
                    const int gm = gm_lo + 8;
                    const int b = gm >> 11, s = gm & (SEQ - 1);
                    *(float2*)(C + (((size_t)(b * NUM_HEADS + h) * SEQ + s) * HEAD_DIM + dh)) = v1;
                }
            } else {
                *(float2*)(C + (size_t)gm_lo * D_MODEL + gn) = v0;
                *(float2*)(C + (size_t)(gm_lo + 8) * D_MODEL + gn) = v1;
            }
        }
    }
}

// ---------------------------------------------------------------------------
// Tensor-core flash attention (tf32 mma.sync, causal), cp.async double-buffered
// KV. K/V pre-rounded tf32 by producer GEMM; Q full fp32 with big+small split.
// Block = 128 q rows x 1 (b,h), 8 warps x 16 rows, KV tile 64.
// ---------------------------------------------------------------------------
#define BQ  128
#define BKV 64
#define KST 68
#define KV_T_BYTES (BKV * KST * 4)        // 17408 (one tensor, one stage)
#define KV_STAGE   (2 * KV_T_BYTES)       // K + V
#define FLASH_SMEM (2 * KV_STAGE)         // 69632

__global__ __launch_bounds__(256, 1) void flash_tc_kernel(
    const float* __restrict__ Qg,
    const float* __restrict__ Kg,
    const float* __restrict__ Vg,
    float* __restrict__ Og)
{
    extern __shared__ char sm[];
    const uint32_t sbase = smem_u32(sm);

    const int bh   = blockIdx.y;
    const int qt   = (int)gridDim.x - 1 - (int)blockIdx.x;  // heavy tiles first
    const int tid  = threadIdx.x;
    const int lane = tid & 31;
    const int wid  = tid >> 5;
    const int g    = lane >> 2;
    const int qd   = lane & 3;
    const int q0   = qt * BQ;
    const int rw   = q0 + wid * 16;

    const float* kbase = Kg + (size_t)bh * SEQ * HEAD_DIM;
    const float* vbase = Vg + (size_t)bh * SEQ * HEAD_DIM;

    // copy mapping: 4 K-chunks + 4 V-chunks of 16B per thread per tile
    auto issue_kv = [&](int j0, int p) {
        const uint32_t kp = sbase + p * KV_STAGE;
        const uint32_t vp = kp + KV_T_BYTES;
#pragma unroll
        for (int t = 0; t < 4; t++) {
            const int c   = tid + t * 256;      // 0..1023
            const int row = c >> 4;
            const int cc  = (c & 15) * 4;
            const uint32_t so = (uint32_t)(row * KST + cc) * 4;
            cp16(kp + so, kbase + (size_t)(j0 + row) * HEAD_DIM + cc);
            cp16(vp + so, vbase + (size_t)(j0 + row) * HEAD_DIM + cc);
        }
        CP_COMMIT();
    };

    // ---- load Q fragments (scaled), split big + small tf32 ----
    uint32_t qbig[8][4], qsml[8][4];
    {
        const float* qb = Qg + ((size_t)bh * SEQ + rw) * HEAD_DIM;
#pragma unroll
        for (int ks = 0; ks < 8; ks++) {
            const int d0 = ks * 8 + qd;
            float v[4];
            v[0] = qb[(size_t)g * HEAD_DIM + d0] * 0.125f;
            v[1] = qb[(size_t)(g + 8) * HEAD_DIM + d0] * 0.125f;
            v[2] = qb[(size_t)g * HEAD_DIM + d0 + 4] * 0.125f;
            v[3] = qb[(size_t)(g + 8) * HEAD_DIM + d0 + 4] * 0.125f;
#pragma unroll
            for (int r = 0; r < 4; r++) {
                uint32_t big = f2tf32(v[r]);
                qbig[ks][r] = big;
                qsml[ks][r] = f2tf32(v[r] - __uint_as_float(big));
            }
        }
    }

    float o[8][4];
#pragma unroll
    for (int nt = 0; nt < 8; nt++)
#pragma unroll
        for (int r = 0; r < 4; r++) o[nt][r] = 0.f;
    float m0 = -1e30f, m1 = -1e30f, l0 = 0.f, l1 = 0.f;

    const int kv_end = q0 + BQ;
    issue_kv(0, 0);

    int p = 0;
    for (int j0 = 0; j0 < kv_end; j0 += BKV, p ^= 1) {
        __syncthreads();   // prev compute on stage p^1 done before overwrite
        const bool more = (j0 + BKV < kv_end);
        if (more) issue_kv(j0 + BKV, p ^ 1); else CP_COMMIT();
        if (more) cp_wait<1>(); else cp_wait<0>();
        __syncthreads();

        if (j0 > rw + 15) continue;   // fully masked for this warp

        const uint32_t* Ks = (const uint32_t*)(sm + p * KV_STAGE);
        const uint32_t* Vs = (const uint32_t*)(sm + p * KV_STAGE + KV_T_BYTES);

        // ---- S = (Q/8) K^T (2-mma compensated) ----
        float sacc[8][4];
#pragma unroll
        for (int nt = 0; nt < 8; nt++)
#pragma unroll
            for (int r = 0; r < 4; r++) sacc[nt][r] = 0.f;

#pragma unroll
        for (int ks = 0; ks < 8; ks++) {
#pragma unroll
            for (int nt = 0; nt < 8; nt++) {
                uint32_t b[2];
                b[0] = Ks[(nt * 8 + g) * KST + ks * 8 + qd];
                b[1] = Ks[(nt * 8 + g) * KST + ks * 8 + qd + 4];
                mma_tf32(sacc[nt], qbig[ks], b);
                mma_tf32(sacc[nt], qsml[ks], b);
            }
        }

        // ---- causal mask (diagonal tiles only) ----
        if (j0 + BKV - 1 > rw) {
            const int rlo = rw + g, rhi = rlo + 8;
#pragma unroll
            for (int nt = 0; nt < 8; nt++) {
                const int col = j0 + nt * 8 + 2 * qd;
                if (col     > rlo) sacc[nt][0] = -1e30f;
                if (col + 1 > rlo) sacc[nt][1] = -1e30f;
                if (col     > rhi) sacc[nt][2] = -1e30f;
                if (col + 1 > rhi) sacc[nt][3] = -1e30f;
            }
        }

        // ---- online softmax ----
        float rmax0 = -1e30f, rmax1 = -1e30f;
#pragma unroll
        for (int nt = 0; nt < 8; nt++) {
            rmax0 = fmaxf(rmax0, fmaxf(sacc[nt][0], sacc[nt][1]));
            rmax1 = fmaxf(rmax1, fmaxf(sacc[nt][2], sacc[nt][3]));
        }
        rmax0 = fmaxf(rmax0, __shfl_xor_sync(0xffffffffu, rmax0, 1));
        rmax0 = fmaxf(rmax0, __shfl_xor_sync(0xffffffffu, rmax0, 2));
        rmax1 = fmaxf(rmax1, __shfl_xor_sync(0xffffffffu, rmax1, 1));
        rmax1 = fmaxf(rmax1, __shfl_xor_sync(0xffffffffu, rmax1, 2));

        const float mn0 = fmaxf(m0, rmax0);
        const float mn1 = fmaxf(m1, rmax1);
        const float corr0 = __expf(m0 - mn0);
        const float corr1 = __expf(m1 - mn1);
        m0 = mn0; m1 = mn1;
        l0 *= corr0; l1 *= corr1;
#pragma unroll
        for (int nt = 0; nt < 8; nt++) {
            o[nt][0] *= corr0; o[nt][1] *= corr0;
            o[nt][2] *= corr1; o[nt][3] *= corr1;
        }
#pragma unroll
        for (int nt = 0; nt < 8; nt++) {
            float p0 = __expf(sacc[nt][0] - mn0);
            float p1 = __expf(sacc[nt][1] - mn0);
            float p2 = __expf(sacc[nt][2] - mn1);
            float p3 = __expf(sacc[nt][3] - mn1);
            l0 += p0 + p1; l1 += p2 + p3;
            sacc[nt][0] = p0; sacc[nt][1] = p1;
            sacc[nt][2] = p2; sacc[nt][3] = p3;
        }

        // ---- O += P V : build P A-frags via quad shuffles ----
        const int srcA = (g << 2) | (qd >> 1);
        const int srcB = srcA + 2;
#pragma unroll
        for (int kt = 0; kt < 8; kt++) {
            float x0 = __shfl_sync(0xffffffffu, sacc[kt][0], srcA);
            float x1 = __shfl_sync(0xffffffffu, sacc[kt][1], srcA);
            float x2 = __shfl_sync(0xffffffffu, sacc[kt][2], srcA);
            float x3 = __shfl_sync(0xffffffffu, sacc[kt][3], srcA);
            float y0 = __shfl_sync(0xffffffffu, sacc[kt][0], srcB);
            float y1 = __shfl_sync(0xffffffffu, sacc[kt][1], srcB);
            float y2 = __shfl_sync(0xffffffffu, sacc[kt][2], srcB);
            float y3 = __shfl_sync(0xffffffffu, sacc[kt][3], srcB);
            uint32_t pa[4];
            pa[0] = f2tf32((qd & 1) ? x1 : x0);
            pa[1] = f2tf32((qd & 1) ? x3 : x2);
            pa[2] = f2tf32((qd & 1) ? y1 : y0);
            pa[3] = f2tf32((qd & 1) ? y3 : y2);
#pragma unroll
            for (int nt = 0; nt < 8; nt++) {
                uint32_t b[2];
                b[0] = Vs[(kt * 8 + qd) * KST + nt * 8 + g];
                b[1] = Vs[(kt * 8 + qd + 4) * KST + nt * 8 + g];
                mma_tf32(o[nt], pa, b);
            }
        }
    }

    // ---- finalize: reduce l, normalize, round to tf32, write [B,S,D] ----
    l0 += __shfl_xor_sync(0xffffffffu, l0, 1);
    l0 += __shfl_xor_sync(0xffffffffu, l0, 2);
    l1 += __shfl_xor_sync(0xffffffffu, l1, 1);
    l1 += __shfl_xor_sync(0xffffffffu, l1, 2);
    const float inv0 = 1.f / l0;
    const float inv1 = 1.f / l1;

    const int b = bh >> 4, h = bh & 15;
    const int row_lo = rw + g;
    float* dlo = Og + ((size_t)(b * SEQ + row_lo)) * D_MODEL + h * HEAD_DIM + 2 * qd;
    float* dhi = Og + ((size_t)(b * SEQ + row_lo + 8)) * D_MODEL + h * HEAD_DIM + 2 * qd;
#pragma unroll
    for (int nt = 0; nt < 8; nt++) {
        float2 v0 = make_float2(__uint_as_float(f2tf32(o[nt][0] * inv0)),
                                __uint_as_float(f2tf32(o[nt][1] * inv0)));
        float2 v1 = make_float2(__uint_as_float(f2tf32(o[nt][2] * inv1)),
                                __uint_as_float(f2tf32(o[nt][3] * inv1)));
        *(float2*)(dlo + nt * 8) = v0;
        *(float2*)(dhi + nt * 8) = v1;
    }
}

// ---------------------------------------------------------------------------
extern "C" void kernel_launch(void* const* d_in, const int* in_sizes, int n_in,
                              void* d_out, int out_size)
{
    (void)in_sizes; (void)n_in; (void)out_size;
    const float* x  = (const float*)d_in[0];
    const float* Wq = (const float*)d_in[1];
    const float* bq = (const float*)d_in[2];
    const float* Wk = (const float*)d_in[3];
    const float* bk = (const float*)d_in[4];
    const float* Wv = (const float*)d_in[5];
    const float* bv = (const float*)d_in[6];
    const float* Wo = (const float*)d_in[7];
    const float* bo = (const float*)d_in[8];
    float* out = (float*)d_out;

    float *gq, *gk, *gv, *gattn, *xt, *wq, *wk, *wv, *wo;
    cudaGetSymbolAddress((void**)&gq,    g_q);
    cudaGetSymbolAddress((void**)&gk,    g_k);
    cudaGetSymbolAddress((void**)&gv,    g_v);
    cudaGetSymbolAddress((void**)&gattn, g_attn);
    cudaGetSymbolAddress((void**)&xt,    g_xt);
    cudaGetSymbolAddress((void**)&wq,    g_wq);
    cudaGetSymbolAddress((void**)&wk,    g_wk);
    cudaGetSymbolAddress((void**)&wv,    g_wv);
    cudaGetSymbolAddress((void**)&wo,    g_wo);

    cudaFuncSetAttribute(mma_gemm2<1,0>, cudaFuncAttributeMaxDynamicSharedMemorySize, GEMM_SMEM);
    cudaFuncSetAttribute(mma_gemm2<1,1>, cudaFuncAttributeMaxDynamicSharedMemorySize, GEMM_SMEM);
    cudaFuncSetAttribute(mma_gemm2<0,0>, cudaFuncAttributeMaxDynamicSharedMemorySize, GEMM_SMEM);
    cudaFuncSetAttribute(flash_tc_kernel, cudaFuncAttributeMaxDynamicSharedMemorySize, FLASH_SMEM);

    round_tf32_kernel<<<NTOK * D_MODEL / 1024, 256>>>(x, xt);
    round_tf32_kernel<<<D_MODEL * D_MODEL / 1024, 256>>>(Wq, wq);
    round_tf32_kernel<<<D_MODEL * D_MODEL / 1024, 256>>>(Wk, wk);
    round_tf32_kernel<<<D_MODEL * D_MODEL / 1024, 256>>>(Wv, wv);
    round_tf32_kernel<<<D_MODEL * D_MODEL / 1024, 256>>>(Wo, wo);

    dim3 gemm_grid(D_MODEL / 128, NTOK / 128);   // (8, 32)
    mma_gemm2<1,0><<<gemm_grid, 256, GEMM_SMEM>>>(xt, wq, bq, gq);
    mma_gemm2<1,1><<<gemm_grid, 256, GEMM_SMEM>>>(xt, wk, bk, gk);
    mma_gemm2<1,1><<<gemm_grid, 256, GEMM_SMEM>>>(xt, wv, bv, gv);

    dim3 flash_grid(SEQ / BQ, BATCH * NUM_HEADS);  // (16, 32)
    flash_tc_kernel<<<flash_grid, 256, FLASH_SMEM>>>(gq, gk, gv, gattn);

    mma_gemm2<0,0><<<gemm_grid, 256, GEMM_SMEM>>>(gattn, wo, bo, out);
}